// round 6
// baseline (speedup 1.0000x reference)
#include <cuda_runtime.h>
#include <cstdint>

// ============================================================================
// out[f32,4096x4096] = mat1[i32] @ mat2[i32] + input[i32], values in [0,16)
// sm_100 BASE toolchain: s8 pack (exact) + mma.sync m16n8k32 s8 (exact)
// R5: CTA tile 128x256, warp tile 64x64 (8 MMA per LDSM, was 2.67).
// ============================================================================

#define MSZ 4096
#define BM 128
#define BN 256
#define BK 64
#define STAGES 4
#define NKT (MSZ / BK)             // 64
#define ROWB 80                    // padded SMEM row: 64 data + 16 pad
#define STAGE_A (BM * ROWB)        // 10240
#define STAGE_B (BN * ROWB)        // 20480
#define STAGE_BYTES (STAGE_A + STAGE_B)      // 30720
#define SMEM_DYN (STAGES * STAGE_BYTES)      // 122880

// Scratch (device globals; no allocation anywhere)
__device__ __align__(128) uint8_t g_packA[(size_t)MSZ * MSZ];   // [M,K] s8
__device__ __align__(128) uint8_t g_packBt[(size_t)MSZ * MSZ];  // [N,K] s8 (B^T)

// ---------------------------------------------------------------- helpers
__device__ __forceinline__ uint32_t smem_u32(const void* p) {
    uint32_t a;
    asm("{ .reg .u64 t; cvta.to.shared.u64 t, %1; cvt.u32.u64 %0, t; }"
        : "=r"(a) : "l"(p));
    return a;
}

#define CPA16(dst, src) \
    asm volatile("cp.async.cg.shared.global [%0], [%1], 16;" :: "r"(dst), "l"(src) : "memory")
#define CPC() asm volatile("cp.async.commit_group;" ::: "memory")
#define CPW(n) asm volatile("cp.async.wait_group %0;" :: "n"(n) : "memory")

#define LDSM4(r0, r1, r2, r3, addr) \
    asm volatile("ldmatrix.sync.aligned.m8n8.x4.shared.b16 {%0,%1,%2,%3}, [%4];" \
                 : "=r"(r0), "=r"(r1), "=r"(r2), "=r"(r3) : "r"(addr))

#define MMA_S8(d, a, b) \
    asm volatile("mma.sync.aligned.m16n8k32.row.col.s32.s8.s8.s32 " \
                 "{%0,%1,%2,%3}, {%4,%5,%6,%7}, {%8,%9}, {%0,%1,%2,%3};" \
                 : "+r"((d)[0]), "+r"((d)[1]), "+r"((d)[2]), "+r"((d)[3]) \
                 : "r"((a)[0]), "r"((a)[1]), "r"((a)[2]), "r"((a)[3]), \
                   "r"((b)[0]), "r"((b)[1]))

// stage loader: A 512 chunks + B 1024 chunks of 16B; 6 per thread (256 thr)
#define LOAD_STAGE(kt, st) do {                                                          \
    const uint32_t sA_ = smbase + (st) * STAGE_BYTES;                                    \
    const uint32_t sB_ = sA_ + STAGE_A;                                                  \
    const uint8_t* pA_ = g_packA  + (size_t)m0 * MSZ + (size_t)(kt) * BK;                \
    const uint8_t* pB_ = g_packBt + (size_t)n0 * MSZ + (size_t)(kt) * BK;                \
    CPA16(sA_ + ldRow * ROWB + ldSeg,         pA_ + (size_t)ldRow * MSZ + ldSeg);        \
    CPA16(sA_ + (ldRow + 64) * ROWB + ldSeg,  pA_ + (size_t)(ldRow + 64) * MSZ + ldSeg); \
    CPA16(sB_ + ldRow * ROWB + ldSeg,         pB_ + (size_t)ldRow * MSZ + ldSeg);        \
    CPA16(sB_ + (ldRow + 64) * ROWB + ldSeg,  pB_ + (size_t)(ldRow + 64) * MSZ + ldSeg); \
    CPA16(sB_ + (ldRow + 128) * ROWB + ldSeg, pB_ + (size_t)(ldRow + 128) * MSZ + ldSeg);\
    CPA16(sB_ + (ldRow + 192) * ROWB + ldSeg, pB_ + (size_t)(ldRow + 192) * MSZ + ldSeg);\
    CPC();                                                                               \
} while (0)

// ---------------------------------------------------------------- pack A
__global__ void packA_kernel(const int* __restrict__ in) {
    size_t i = (size_t)blockIdx.x * blockDim.x + threadIdx.x;
    int4 v = ((const int4*)in)[i];
    uchar4 r;
    r.x = (uint8_t)v.x; r.y = (uint8_t)v.y; r.z = (uint8_t)v.z; r.w = (uint8_t)v.w;
    ((uchar4*)g_packA)[i] = r;
}

// ---------------------------------------------------------------- pack B^T
__global__ void packBt_kernel(const int* __restrict__ B) {
    __shared__ uint8_t tsm[32][132];
    const int kb = blockIdx.x * 128;
    const int nb = blockIdx.y * 32;
    const int t = threadIdx.x;
    const int kloc = t >> 5;
    const int nloc = t & 31;
    #pragma unroll
    for (int i = 0; i < 16; i++) {
        int k = kloc + i * 8;
        tsm[nloc][k] = (uint8_t)B[(size_t)(kb + k) * MSZ + nb + nloc];
    }
    __syncthreads();
    const int k4 = (t & 31) * 4;
    const int nrow = t >> 5;
    #pragma unroll
    for (int i = 0; i < 4; i++) {
        int n = nrow + i * 8;
        uchar4 v;
        v.x = tsm[n][k4]; v.y = tsm[n][k4 + 1]; v.z = tsm[n][k4 + 2]; v.w = tsm[n][k4 + 3];
        *(uchar4*)&g_packBt[(size_t)(nb + n) * MSZ + kb + k4] = v;
    }
}

// ---------------------------------------------------------------- GEMM
// 256 threads, 8 warps 2(m) x 4(n); warp tile 64x64; CTA tile 128x256x64.
__global__ void __launch_bounds__(256, 1)
gemm_kernel(const int* __restrict__ gIn, float* __restrict__ gOut) {
    extern __shared__ uint8_t dsm[];
    const uint32_t smbase = smem_u32(dsm);

    const int tid = threadIdx.x;
    const int l = tid & 31;
    const int warp = tid >> 5;
    const int wm = warp >> 2;        // 0..1
    const int wn = warp & 3;         // 0..3
    const int m0 = blockIdx.y * BM;
    const int n0 = blockIdx.x * BN;

    const int ldRow = tid >> 2;          // 0..63
    const int ldSeg = (tid & 3) * 16;    // 0/16/32/48

    // ldmatrix lane-address components (m16n8k32 fragment layout)
    const int aRowL = (l & 7) + ((l >> 3) & 1) * 8;
    const int aChk  = ((l >> 4) & 1) * 16;
    const int bRowL = (l & 7) + ((l >> 4) & 1) * 8;
    const int bChk  = ((l >> 3) & 1) * 16;

    int acc[4][8][4];
    #pragma unroll
    for (int mi = 0; mi < 4; mi++)
        #pragma unroll
        for (int ni = 0; ni < 8; ni++)
            #pragma unroll
            for (int r = 0; r < 4; r++) acc[mi][ni][r] = 0;

    // prologue: 3 stages in flight
    LOAD_STAGE(0, 0);
    LOAD_STAGE(1, 1);
    LOAD_STAGE(2, 2);

    for (int kt = 0; kt < NKT; kt++) {
        CPW(STAGES - 2);
        __syncthreads();

        if (kt + STAGES - 1 < NKT) { LOAD_STAGE(kt + STAGES - 1, (kt + STAGES - 1) % STAGES); }
        else { CPC(); }

        const uint32_t sA = smbase + (kt % STAGES) * STAGE_BYTES;
        const uint32_t sB = sA + STAGE_A;

        #pragma unroll
        for (int ks = 0; ks < 2; ks++) {
            uint32_t a[4][4], b[8][2];
            #pragma unroll
            for (int mi = 0; mi < 4; mi++) {
                uint32_t addr = sA + (uint32_t)(wm * 64 + mi * 16 + aRowL) * ROWB
                              + aChk + ks * 32;
                LDSM4(a[mi][0], a[mi][1], a[mi][2], a[mi][3], addr);
            }
            #pragma unroll
            for (int np = 0; np < 4; np++) {
                uint32_t r0, r1, r2, r3;
                uint32_t addr = sB + (uint32_t)(wn * 64 + np * 16 + bRowL) * ROWB
                              + bChk + ks * 32;
                LDSM4(r0, r1, r2, r3, addr);
                b[np * 2 + 0][0] = r0; b[np * 2 + 0][1] = r1;
                b[np * 2 + 1][0] = r2; b[np * 2 + 1][1] = r3;
            }
            #pragma unroll
            for (int mi = 0; mi < 4; mi++)
                #pragma unroll
                for (int ni = 0; ni < 8; ni++)
                    MMA_S8(acc[mi][ni], a[mi], b[ni]);
        }
    }

    // Epilogue: int add (exact) then f32 convert; float2 stores.
    const int crow = l >> 2;
    const int ccol = (l & 3) * 2;
    #pragma unroll
    for (int mi = 0; mi < 4; mi++) {
        #pragma unroll
        for (int ni = 0; ni < 8; ni++) {
            const int row = m0 + wm * 64 + mi * 16 + crow;
            const int col = n0 + wn * 64 + ni * 8 + ccol;
            const size_t gi = (size_t)row * MSZ + col;
            const int2 in0 = *(const int2*)&gIn[gi];
            const int2 in1 = *(const int2*)&gIn[gi + (size_t)8 * MSZ];
            float2 o0, o1;
            o0.x = (float)(acc[mi][ni][0] + in0.x);
            o0.y = (float)(acc[mi][ni][1] + in0.y);
            o1.x = (float)(acc[mi][ni][2] + in1.x);
            o1.y = (float)(acc[mi][ni][3] + in1.y);
            *(float2*)&gOut[gi] = o0;
            *(float2*)&gOut[gi + (size_t)8 * MSZ] = o1;
        }
    }
}

// ---------------------------------------------------------------- launch
extern "C" void kernel_launch(void* const* d_in, const int* in_sizes, int n_in,
                              void* d_out, int out_size) {
    const int* inp  = (const int*)d_in[0];   // input_tensor [M,N]
    const int* mat1 = (const int*)d_in[1];   // [M,K]
    const int* mat2 = (const int*)d_in[2];   // [K,N]
    float* out = (float*)d_out;

    packA_kernel<<<(MSZ * MSZ / 4) / 256, 256>>>(mat1);
    packBt_kernel<<<dim3(MSZ / 128, MSZ / 32), 256>>>(mat2);

    static int smem_set = 0;
    if (!smem_set) {
        cudaFuncSetAttribute(gemm_kernel, cudaFuncAttributeMaxDynamicSharedMemorySize, SMEM_DYN);
        smem_set = 1;
    }
    gemm_kernel<<<dim3(MSZ / BN, MSZ / BM), 256, SMEM_DYN>>>(inp, out);
}

// round 7
// speedup vs baseline: 1.2717x; 1.2717x over previous
#include <cuda_runtime.h>
#include <cstdint>

// ============================================================================
// out[f32,4096x4096] = mat1[i32] @ mat2[i32] + input[i32], values in [0,16)
// sm_100 BASE toolchain: s8 pack (exact) + mma.sync m16n8k32 s8 (exact)
// R7: CTA 128x128, 4 warps (2x2) of 64x64, 4-stage cp.async, 2 CTAs/SM.
// ============================================================================

#define MSZ 4096
#define BM 128
#define BN 128
#define BK 64
#define STAGES 4
#define NKT (MSZ / BK)             // 64
#define ROWB 80                    // padded SMEM row: 64 data + 16 pad
#define STAGE_A (BM * ROWB)        // 10240
#define STAGE_B (BN * ROWB)        // 10240
#define STAGE_BYTES (STAGE_A + STAGE_B)      // 20480
#define SMEM_DYN (STAGES * STAGE_BYTES)      // 81920  -> 2 CTAs/SM

// Scratch (device globals; no allocation anywhere)
__device__ __align__(128) uint8_t g_packA[(size_t)MSZ * MSZ];   // [M,K] s8
__device__ __align__(128) uint8_t g_packBt[(size_t)MSZ * MSZ];  // [N,K] s8 (B^T)

// ---------------------------------------------------------------- helpers
__device__ __forceinline__ uint32_t smem_u32(const void* p) {
    uint32_t a;
    asm("{ .reg .u64 t; cvta.to.shared.u64 t, %1; cvt.u32.u64 %0, t; }"
        : "=r"(a) : "l"(p));
    return a;
}

#define CPA16(dst, src) \
    asm volatile("cp.async.cg.shared.global [%0], [%1], 16;" :: "r"(dst), "l"(src) : "memory")
#define CPC() asm volatile("cp.async.commit_group;" ::: "memory")
#define CPW(n) asm volatile("cp.async.wait_group %0;" :: "n"(n) : "memory")

#define LDSM4(r0, r1, r2, r3, addr) \
    asm volatile("ldmatrix.sync.aligned.m8n8.x4.shared.b16 {%0,%1,%2,%3}, [%4];" \
                 : "=r"(r0), "=r"(r1), "=r"(r2), "=r"(r3) : "r"(addr))

#define MMA_S8(d, a, b) \
    asm volatile("mma.sync.aligned.m16n8k32.row.col.s32.s8.s8.s32 " \
                 "{%0,%1,%2,%3}, {%4,%5,%6,%7}, {%8,%9}, {%0,%1,%2,%3};" \
                 : "+r"((d)[0]), "+r"((d)[1]), "+r"((d)[2]), "+r"((d)[3]) \
                 : "r"((a)[0]), "r"((a)[1]), "r"((a)[2]), "r"((a)[3]), \
                   "r"((b)[0]), "r"((b)[1]))

// stage loader: 128 threads; A 512 + B 512 16B chunks; 8 per thread
#define LOAD_STAGE(kt, st) do {                                                          \
    const uint32_t sA_ = smbase + (st) * STAGE_BYTES;                                    \
    const uint32_t sB_ = sA_ + STAGE_A;                                                  \
    const uint8_t* pA_ = g_packA  + (size_t)m0 * MSZ + (size_t)(kt) * BK;                \
    const uint8_t* pB_ = g_packBt + (size_t)n0 * MSZ + (size_t)(kt) * BK;                \
    CPA16(sA_ + ldRow * ROWB + ldSeg,         pA_ + (size_t)ldRow * MSZ + ldSeg);        \
    CPA16(sA_ + (ldRow + 32) * ROWB + ldSeg,  pA_ + (size_t)(ldRow + 32) * MSZ + ldSeg); \
    CPA16(sA_ + (ldRow + 64) * ROWB + ldSeg,  pA_ + (size_t)(ldRow + 64) * MSZ + ldSeg); \
    CPA16(sA_ + (ldRow + 96) * ROWB + ldSeg,  pA_ + (size_t)(ldRow + 96) * MSZ + ldSeg); \
    CPA16(sB_ + ldRow * ROWB + ldSeg,         pB_ + (size_t)ldRow * MSZ + ldSeg);        \
    CPA16(sB_ + (ldRow + 32) * ROWB + ldSeg,  pB_ + (size_t)(ldRow + 32) * MSZ + ldSeg); \
    CPA16(sB_ + (ldRow + 64) * ROWB + ldSeg,  pB_ + (size_t)(ldRow + 64) * MSZ + ldSeg); \
    CPA16(sB_ + (ldRow + 96) * ROWB + ldSeg,  pB_ + (size_t)(ldRow + 96) * MSZ + ldSeg); \
    CPC();                                                                               \
} while (0)

// ---------------------------------------------------------------- pack A
__global__ void packA_kernel(const int* __restrict__ in) {
    size_t i = (size_t)blockIdx.x * blockDim.x + threadIdx.x;
    int4 v = ((const int4*)in)[i];
    uchar4 r;
    r.x = (uint8_t)v.x; r.y = (uint8_t)v.y; r.z = (uint8_t)v.z; r.w = (uint8_t)v.w;
    ((uchar4*)g_packA)[i] = r;
}

// ---------------------------------------------------------------- pack B^T
__global__ void packBt_kernel(const int* __restrict__ B) {
    __shared__ uint8_t tsm[32][132];
    const int kb = blockIdx.x * 128;
    const int nb = blockIdx.y * 32;
    const int t = threadIdx.x;
    const int kloc = t >> 5;
    const int nloc = t & 31;
    #pragma unroll
    for (int i = 0; i < 16; i++) {
        int k = kloc + i * 8;
        tsm[nloc][k] = (uint8_t)B[(size_t)(kb + k) * MSZ + nb + nloc];
    }
    __syncthreads();
    const int k4 = (t & 31) * 4;
    const int nrow = t >> 5;
    #pragma unroll
    for (int i = 0; i < 4; i++) {
        int n = nrow + i * 8;
        uchar4 v;
        v.x = tsm[n][k4]; v.y = tsm[n][k4 + 1]; v.z = tsm[n][k4 + 2]; v.w = tsm[n][k4 + 3];
        *(uchar4*)&g_packBt[(size_t)(nb + n) * MSZ + kb + k4] = v;
    }
}

// ---------------------------------------------------------------- GEMM
// 128 threads, 4 warps 2(m) x 2(n); warp tile 64x64; CTA tile 128x128x64.
__global__ void __launch_bounds__(128, 2)
gemm_kernel(const int* __restrict__ gIn, float* __restrict__ gOut) {
    extern __shared__ uint8_t dsm[];
    const uint32_t smbase = smem_u32(dsm);

    const int tid = threadIdx.x;
    const int l = tid & 31;
    const int warp = tid >> 5;
    const int wm = warp >> 1;        // 0..1
    const int wn = warp & 1;         // 0..1
    const int m0 = blockIdx.y * BM;
    const int n0 = blockIdx.x * BN;

    const int ldRow = tid >> 2;          // 0..31
    const int ldSeg = (tid & 3) * 16;    // 0/16/32/48

    // ldmatrix lane-address components (m16n8k32 fragment layout)
    const int aRowL = (l & 7) + ((l >> 3) & 1) * 8;
    const int aChk  = ((l >> 4) & 1) * 16;
    const int bRowL = (l & 7) + ((l >> 4) & 1) * 8;
    const int bChk  = ((l >> 3) & 1) * 16;

    int acc[4][8][4];
    #pragma unroll
    for (int mi = 0; mi < 4; mi++)
        #pragma unroll
        for (int ni = 0; ni < 8; ni++)
            #pragma unroll
            for (int r = 0; r < 4; r++) acc[mi][ni][r] = 0;

    // prologue: 3 stages in flight
    LOAD_STAGE(0, 0);
    LOAD_STAGE(1, 1);
    LOAD_STAGE(2, 2);

    for (int kt = 0; kt < NKT; kt++) {
        CPW(STAGES - 2);
        __syncthreads();

        if (kt + STAGES - 1 < NKT) { LOAD_STAGE(kt + STAGES - 1, (kt + STAGES - 1) % STAGES); }
        else { CPC(); }

        const uint32_t sA = smbase + (kt % STAGES) * STAGE_BYTES;
        const uint32_t sB = sA + STAGE_A;

        #pragma unroll
        for (int ks = 0; ks < 2; ks++) {
            uint32_t a[4][4], b[8][2];
            #pragma unroll
            for (int mi = 0; mi < 4; mi++) {
                uint32_t addr = sA + (uint32_t)(wm * 64 + mi * 16 + aRowL) * ROWB
                              + aChk + ks * 32;
                LDSM4(a[mi][0], a[mi][1], a[mi][2], a[mi][3], addr);
            }
            #pragma unroll
            for (int np = 0; np < 4; np++) {
                uint32_t r0, r1, r2, r3;
                uint32_t addr = sB + (uint32_t)(wn * 64 + np * 16 + bRowL) * ROWB
                              + bChk + ks * 32;
                LDSM4(r0, r1, r2, r3, addr);
                b[np * 2 + 0][0] = r0; b[np * 2 + 0][1] = r1;
                b[np * 2 + 1][0] = r2; b[np * 2 + 1][1] = r3;
            }
            #pragma unroll
            for (int mi = 0; mi < 4; mi++)
                #pragma unroll
                for (int ni = 0; ni < 8; ni++)
                    MMA_S8(acc[mi][ni], a[mi], b[ni]);
        }
    }

    // Epilogue: int add (exact) then f32 convert; float2 stores.
    const int crow = l >> 2;
    const int ccol = (l & 3) * 2;
    #pragma unroll
    for (int mi = 0; mi < 4; mi++) {
        #pragma unroll
        for (int ni = 0; ni < 8; ni++) {
            const int row = m0 + wm * 64 + mi * 16 + crow;
            const int col = n0 + wn * 64 + ni * 8 + ccol;
            const size_t gi = (size_t)row * MSZ + col;
            const int2 in0 = *(const int2*)&gIn[gi];
            const int2 in1 = *(const int2*)&gIn[gi + (size_t)8 * MSZ];
            float2 o0, o1;
            o0.x = (float)(acc[mi][ni][0] + in0.x);
            o0.y = (float)(acc[mi][ni][1] + in0.y);
            o1.x = (float)(acc[mi][ni][2] + in1.x);
            o1.y = (float)(acc[mi][ni][3] + in1.y);
            *(float2*)&gOut[gi] = o0;
            *(float2*)&gOut[gi + (size_t)8 * MSZ] = o1;
        }
    }
}

// ---------------------------------------------------------------- launch
extern "C" void kernel_launch(void* const* d_in, const int* in_sizes, int n_in,
                              void* d_out, int out_size) {
    const int* inp  = (const int*)d_in[0];   // input_tensor [M,N]
    const int* mat1 = (const int*)d_in[1];   // [M,K]
    const int* mat2 = (const int*)d_in[2];   // [K,N]
    float* out = (float*)d_out;

    packA_kernel<<<(MSZ * MSZ / 4) / 256, 256>>>(mat1);
    packBt_kernel<<<dim3(MSZ / 128, MSZ / 32), 256>>>(mat2);

    static int smem_set = 0;
    if (!smem_set) {
        cudaFuncSetAttribute(gemm_kernel, cudaFuncAttributeMaxDynamicSharedMemorySize, SMEM_DYN);
        smem_set = 1;
    }
    gemm_kernel<<<dim3(MSZ / BN, MSZ / BM), 128, SMEM_DYN>>>(inp, out);
}

// round 8
// speedup vs baseline: 1.2875x; 1.0124x over previous
#include <cuda_runtime.h>
#include <cstdint>

// ============================================================================
// out[f32,4096x4096] = mat1[i32] @ mat2[i32] + input[i32], values in [0,16)
// sm_100 BASE toolchain: s8 pack (exact) + mma.sync m16n8k32 s8 (exact)
// R8: fused pack kernel; GEMM BK=128 (4 ks per barrier), 3 stages, 2 CTAs/SM.
// ============================================================================

#define MSZ 4096
#define BM 128
#define BN 128
#define BK 128
#define STAGES 3
#define NKT (MSZ / BK)             // 32
#define ROWB 144                   // padded SMEM row: 128 data + 16 pad
#define STAGE_A (BM * ROWB)        // 18432
#define STAGE_B (BN * ROWB)        // 18432
#define STAGE_BYTES (STAGE_A + STAGE_B)      // 36864
#define SMEM_DYN (STAGES * STAGE_BYTES)      // 110592 -> 2 CTAs/SM (221KB)

// Scratch (device globals; no allocation anywhere)
__device__ __align__(128) uint8_t g_packA[(size_t)MSZ * MSZ];   // [M,K] s8
__device__ __align__(128) uint8_t g_packBt[(size_t)MSZ * MSZ];  // [N,K] s8 (B^T)

// ---------------------------------------------------------------- helpers
__device__ __forceinline__ uint32_t smem_u32(const void* p) {
    uint32_t a;
    asm("{ .reg .u64 t; cvta.to.shared.u64 t, %1; cvt.u32.u64 %0, t; }"
        : "=r"(a) : "l"(p));
    return a;
}

#define CPA16(dst, src) \
    asm volatile("cp.async.cg.shared.global [%0], [%1], 16;" :: "r"(dst), "l"(src) : "memory")
#define CPC() asm volatile("cp.async.commit_group;" ::: "memory")
#define CPW(n) asm volatile("cp.async.wait_group %0;" :: "n"(n) : "memory")

#define LDSM4(r0, r1, r2, r3, addr) \
    asm volatile("ldmatrix.sync.aligned.m8n8.x4.shared.b16 {%0,%1,%2,%3}, [%4];" \
                 : "=r"(r0), "=r"(r1), "=r"(r2), "=r"(r3) : "r"(addr))

#define MMA_S8(d, a, b) \
    asm volatile("mma.sync.aligned.m16n8k32.row.col.s32.s8.s8.s32 " \
                 "{%0,%1,%2,%3}, {%4,%5,%6,%7}, {%8,%9}, {%0,%1,%2,%3};" \
                 : "+r"((d)[0]), "+r"((d)[1]), "+r"((d)[2]), "+r"((d)[3]) \
                 : "r"((a)[0]), "r"((a)[1]), "r"((a)[2]), "r"((a)[3]), \
                   "r"((b)[0]), "r"((b)[1]))

// stage loader: 128 threads; A 1024 + B 1024 16B chunks; 16 per thread.
// row stride 16 over 128 rows, seg = (tid&7)*16 within the 128B row.
#define LOAD_STAGE(kt, st) do {                                                           \
    const uint32_t sA_ = smbase + (st) * STAGE_BYTES;                                     \
    const uint32_t sB_ = sA_ + STAGE_A;                                                   \
    const uint8_t* pA_ = g_packA  + (size_t)m0 * MSZ + (size_t)(kt) * BK;                 \
    const uint8_t* pB_ = g_packBt + (size_t)n0 * MSZ + (size_t)(kt) * BK;                 \
    _Pragma("unroll")                                                                     \
    for (int i_ = 0; i_ < 8; i_++) {                                                      \
        const int row_ = ldRow + i_ * 16;                                                 \
        CPA16(sA_ + row_ * ROWB + ldSeg, pA_ + (size_t)row_ * MSZ + ldSeg);               \
        CPA16(sB_ + row_ * ROWB + ldSeg, pB_ + (size_t)row_ * MSZ + ldSeg);               \
    }                                                                                     \
    CPC();                                                                                \
} while (0)

// ---------------------------------------------------------------- fused pack
// blocks [0, 16384): packA (256 thr, 1024 int4 elems each)
// blocks [16384, 20480): packBt tiles 128(k) x 32(n)
__global__ void pack_kernel(const int* __restrict__ A, const int* __restrict__ B) {
    if (blockIdx.x < 16384) {
        size_t i = (size_t)blockIdx.x * 256 + threadIdx.x;
        int4 v = ((const int4*)A)[i];
        uchar4 r;
        r.x = (uint8_t)v.x; r.y = (uint8_t)v.y; r.z = (uint8_t)v.z; r.w = (uint8_t)v.w;
        ((uchar4*)g_packA)[i] = r;
    } else {
        __shared__ uint8_t tsm[32][132];
        const int b2 = blockIdx.x - 16384;
        const int kb = (b2 & 31) * 128;
        const int nb = (b2 >> 5) * 32;
        const int t = threadIdx.x;
        const int kloc = t >> 5;
        const int nloc = t & 31;
        #pragma unroll
        for (int i = 0; i < 16; i++) {
            int k = kloc + i * 8;
            tsm[nloc][k] = (uint8_t)B[(size_t)(kb + k) * MSZ + nb + nloc];
        }
        __syncthreads();
        const int k4 = (t & 31) * 4;
        const int nrow = t >> 5;
        #pragma unroll
        for (int i = 0; i < 4; i++) {
            int n = nrow + i * 8;
            uchar4 v;
            v.x = tsm[n][k4]; v.y = tsm[n][k4 + 1]; v.z = tsm[n][k4 + 2]; v.w = tsm[n][k4 + 3];
            *(uchar4*)&g_packBt[(size_t)(nb + n) * MSZ + kb + k4] = v;
        }
    }
}

// ---------------------------------------------------------------- GEMM
// 128 threads, 4 warps 2(m) x 2(n); warp tile 64x64; CTA tile 128x128x128.
__global__ void __launch_bounds__(128, 2)
gemm_kernel(const int* __restrict__ gIn, float* __restrict__ gOut) {
    extern __shared__ uint8_t dsm[];
    const uint32_t smbase = smem_u32(dsm);

    const int tid = threadIdx.x;
    const int l = tid & 31;
    const int warp = tid >> 5;
    const int wm = warp >> 1;        // 0..1
    const int wn = warp & 1;         // 0..1
    const int m0 = blockIdx.y * BM;
    const int n0 = blockIdx.x * BN;

    const int ldRow = tid >> 3;          // 0..15
    const int ldSeg = (tid & 7) * 16;    // 0..112

    // ldmatrix lane-address components (m16n8k32 fragment layout)
    const int aRowL = (l & 7) + ((l >> 3) & 1) * 8;
    const int aChk  = ((l >> 4) & 1) * 16;
    const int bRowL = (l & 7) + ((l >> 4) & 1) * 8;
    const int bChk  = ((l >> 3) & 1) * 16;

    int acc[4][8][4];
    #pragma unroll
    for (int mi = 0; mi < 4; mi++)
        #pragma unroll
        for (int ni = 0; ni < 8; ni++)
            #pragma unroll
            for (int r = 0; r < 4; r++) acc[mi][ni][r] = 0;

    // prologue: 2 stages in flight
    LOAD_STAGE(0, 0);
    LOAD_STAGE(1, 1);

    for (int kt = 0; kt < NKT; kt++) {
        CPW(STAGES - 2);          // stage kt%3's group complete
        __syncthreads();

        if (kt + STAGES - 1 < NKT) { LOAD_STAGE(kt + STAGES - 1, (kt + STAGES - 1) % STAGES); }
        else { CPC(); }

        const uint32_t sA = smbase + (kt % STAGES) * STAGE_BYTES;
        const uint32_t sB = sA + STAGE_A;

        #pragma unroll
        for (int ks = 0; ks < 4; ks++) {
            uint32_t a[4][4], b[8][2];
            #pragma unroll
            for (int mi = 0; mi < 4; mi++) {
                uint32_t addr = sA + (uint32_t)(wm * 64 + mi * 16 + aRowL) * ROWB
                              + aChk + ks * 32;
                LDSM4(a[mi][0], a[mi][1], a[mi][2], a[mi][3], addr);
            }
            #pragma unroll
            for (int np = 0; np < 4; np++) {
                uint32_t r0, r1, r2, r3;
                uint32_t addr = sB + (uint32_t)(wn * 64 + np * 16 + bRowL) * ROWB
                              + bChk + ks * 32;
                LDSM4(r0, r1, r2, r3, addr);
                b[np * 2 + 0][0] = r0; b[np * 2 + 0][1] = r1;
                b[np * 2 + 1][0] = r2; b[np * 2 + 1][1] = r3;
            }
            #pragma unroll
            for (int mi = 0; mi < 4; mi++)
                #pragma unroll
                for (int ni = 0; ni < 8; ni++)
                    MMA_S8(acc[mi][ni], a[mi], b[ni]);
        }
    }

    // Epilogue: int add (exact) then f32 convert; float2 stores.
    const int crow = l >> 2;
    const int ccol = (l & 3) * 2;
    #pragma unroll
    for (int mi = 0; mi < 4; mi++) {
        #pragma unroll
        for (int ni = 0; ni < 8; ni++) {
            const int row = m0 + wm * 64 + mi * 16 + crow;
            const int col = n0 + wn * 64 + ni * 8 + ccol;
            const size_t gi = (size_t)row * MSZ + col;
            const int2 in0 = *(const int2*)&gIn[gi];
            const int2 in1 = *(const int2*)&gIn[gi + (size_t)8 * MSZ];
            float2 o0, o1;
            o0.x = (float)(acc[mi][ni][0] + in0.x);
            o0.y = (float)(acc[mi][ni][1] + in0.y);
            o1.x = (float)(acc[mi][ni][2] + in1.x);
            o1.y = (float)(acc[mi][ni][3] + in1.y);
            *(float2*)&gOut[gi] = o0;
            *(float2*)&gOut[gi + (size_t)8 * MSZ] = o1;
        }
    }
}

// ---------------------------------------------------------------- launch
extern "C" void kernel_launch(void* const* d_in, const int* in_sizes, int n_in,
                              void* d_out, int out_size) {
    const int* inp  = (const int*)d_in[0];   // input_tensor [M,N]
    const int* mat1 = (const int*)d_in[1];   // [M,K]
    const int* mat2 = (const int*)d_in[2];   // [K,N]
    float* out = (float*)d_out;

    pack_kernel<<<16384 + 4096, 256>>>(mat1, mat2);

    static int smem_set = 0;
    if (!smem_set) {
        cudaFuncSetAttribute(gemm_kernel, cudaFuncAttributeMaxDynamicSharedMemorySize, SMEM_DYN);
        smem_set = 1;
    }
    gemm_kernel<<<dim3(MSZ / BN, MSZ / BM), 128, SMEM_DYN>>>(inp, out);
}